// round 3
// baseline (speedup 1.0000x reference)
#include <cuda_runtime.h>
#include <stdint.h>

// Problem shape (GateLayer_28200755265636): x (4096,4096) f32, idx_l/idx_r (16384,),
// alpha (16384,3) f32, y (4096,16384) f32.
#define MDIM    4096
#define GMAX    16384
#define ROWS    8
#define RSTRIDE (MDIM + 1)          // 4097: row r shifts LDS banks by r (4097 % 32 == 1)

// Device scratch (static allocation — no cudaMalloc allowed)
__device__ __align__(16) int    g_il[GMAX];
__device__ __align__(16) int    g_ir[GMAX];
__device__ __align__(16) float2 g_cf[GMAX];
__device__ int g_is64;

// ---------------------------------------------------------------------------
// Kernel 0: detect whether idx buffers are int64 or int32.
// If int64 (values < 4096, nonneg), every odd 32-bit word of the buffer is 0.
// If int32, the odd words are random values in [0, 4096) -> OR != 0 w.h.p.
// Reading the first G 32-bit words is safe in both cases.
// ---------------------------------------------------------------------------
__global__ void detect_kernel(const unsigned int* il, const unsigned int* ir, int G) {
    __shared__ unsigned int red[256];
    unsigned int acc = 0;
    for (int i = threadIdx.x * 2 + 1; i < G; i += blockDim.x * 2) {
        acc |= il[i];
        acc |= ir[i];
    }
    red[threadIdx.x] = acc;
    __syncthreads();
    for (int s = 128; s > 0; s >>= 1) {
        if (threadIdx.x < s) red[threadIdx.x] |= red[threadIdx.x + s];
        __syncthreads();
    }
    if (threadIdx.x == 0) g_is64 = (red[0] == 0u) ? 1 : 0;
}

// ---------------------------------------------------------------------------
// Kernel 1: fold softmax(alpha) into two per-g coefficients, idx -> int32.
//   y = w0*ab + w1*(s-ab) + w2*(s-2ab) = (w0-w1-2w2)*ab + (w1+w2)*s
// ---------------------------------------------------------------------------
__global__ void prep_kernel(const unsigned int* il_raw, const unsigned int* ir_raw,
                            const float* __restrict__ alpha, int G) {
    int g = blockIdx.x * blockDim.x + threadIdx.x;
    if (g >= G) return;
    int is64 = g_is64;
    int il, ir;
    if (is64) {
        il = (int)il_raw[2 * g];     // low word of little-endian int64
        ir = (int)ir_raw[2 * g];
    } else {
        il = (int)il_raw[g];
        ir = (int)ir_raw[g];
    }
    g_il[g] = il;
    g_ir[g] = ir;

    float a0 = alpha[3 * g + 0];
    float a1 = alpha[3 * g + 1];
    float a2 = alpha[3 * g + 2];
    float m  = fmaxf(a0, fmaxf(a1, a2));
    float e0 = expf(a0 - m), e1 = expf(a1 - m), e2 = expf(a2 - m);
    float inv = 1.0f / (e0 + e1 + e2);
    float w0 = e0 * inv, w1 = e1 * inv, w2 = e2 * inv;
    g_cf[g] = make_float2(w0 - w1 - 2.0f * w2, w1 + w2);
}

// ---------------------------------------------------------------------------
// Kernel 2: main gather/gate kernel.
// Each block: stages ROWS=8 rows of x in SMEM (stride 4097 -> bank shift per row),
// then sweeps a g-range. Lane mapping: rsub = lane&7 (row), gsub = lane>>3.
// Each thread handles 4 consecutive g -> int4/float4 side loads, float4 stores.
// 8 lanes share each g, so one LDS gather instruction touches 4 random runs of
// 8 consecutive banks -> low conflict degree.
// ---------------------------------------------------------------------------
__global__ __launch_bounds__(1024, 1)
void gate_kernel(const float* __restrict__ x, float* __restrict__ y,
                 int G, int gPerBlock) {
    extern __shared__ float sm[];
    const int tid    = threadIdx.x;
    const int row0   = blockIdx.x * ROWS;
    const int gstart = blockIdx.y * gPerBlock;

    // Stage 8 rows (x is row-major, rows 16 KB each): float4 global loads,
    // scalar SMEM stores (odd row stride prevents vector STS).
    const float4* __restrict__ x4 = (const float4*)(x + (size_t)row0 * MDIM);
    #pragma unroll
    for (int i = tid; i < ROWS * (MDIM / 4); i += 1024) {
        int r  = i >> 10;            // MDIM/4 == 1024
        int c4 = i & 1023;
        float4 v = x4[r * (MDIM / 4) + c4];
        float* dst = sm + r * RSTRIDE + c4 * 4;
        dst[0] = v.x; dst[1] = v.y; dst[2] = v.z; dst[3] = v.w;
    }
    __syncthreads();

    const int warp = tid >> 5;
    const int lane = tid & 31;
    const int rsub = lane & 7;       // row within the 8-row tile
    const int gsub = lane >> 3;      // which 4-g chunk within the warp's 16 g

    const float* __restrict__ smrow = sm + rsub * RSTRIDE;
    float* __restrict__ yrow = y + (size_t)(row0 + rsub) * G;

    const int gPerIter = 32 * 16;    // 32 warps x 16 g each = 512 g per block-iter
    for (int gb = gstart + warp * 16 + gsub * 4;
         gb < gstart + gPerBlock;
         gb += gPerIter) {
        int4   il  = *(const int4*)&g_il[gb];
        int4   ir  = *(const int4*)&g_ir[gb];
        float4 c01 = ((const float4*)g_cf)[(gb >> 1) + 0];  // (c_ab,c_s) for g, g+1
        float4 c23 = ((const float4*)g_cf)[(gb >> 1) + 1];  // (c_ab,c_s) for g+2, g+3

        float a, b;
        float4 o;
        a = smrow[il.x]; b = smrow[ir.x]; o.x = fmaf(c01.x, a * b, c01.y * (a + b));
        a = smrow[il.y]; b = smrow[ir.y]; o.y = fmaf(c01.z, a * b, c01.w * (a + b));
        a = smrow[il.z]; b = smrow[ir.z]; o.z = fmaf(c23.x, a * b, c23.y * (a + b));
        a = smrow[il.w]; b = smrow[ir.w]; o.w = fmaf(c23.z, a * b, c23.w * (a + b));

        *(float4*)&yrow[gb] = o;
    }
}

// ---------------------------------------------------------------------------
extern "C" void kernel_launch(void* const* d_in, const int* in_sizes, int n_in,
                              void* d_out, int out_size) {
    const float*        x     = (const float*)d_in[0];
    const unsigned int* il    = (const unsigned int*)d_in[1];
    const unsigned int* ir    = (const unsigned int*)d_in[2];
    const float*        alpha = (const float*)d_in[3];
    float*              y     = (float*)d_out;

    const int G = in_sizes[1];               // 16384
    const int B = in_sizes[0] / MDIM;        // 4096

    detect_kernel<<<1, 256>>>(il, ir, G);
    prep_kernel<<<(G + 255) / 256, 256>>>(il, ir, alpha, G);

    const int smemBytes = ROWS * RSTRIDE * (int)sizeof(float);  // 131104 B
    cudaFuncSetAttribute(gate_kernel, cudaFuncAttributeMaxDynamicSharedMemorySize,
                         smemBytes);

    dim3 grid(B / ROWS, 2);                  // (512, 2): g-space split for wave balance
    gate_kernel<<<grid, 1024, smemBytes>>>(x, y, G, G / 2);
}

// round 4
// speedup vs baseline: 2.0415x; 2.0415x over previous
#include <cuda_runtime.h>
#include <stdint.h>

// GateLayer: x (4096,4096) f32, idx_l/idx_r (16384,) int, alpha (16384,3) f32,
// y (4096,16384) f32.
#define MDIM    4096
#define GMAX    16384
#define ROWS    8

// Static device scratch (no cudaMalloc allowed)
__device__ __align__(16) int    g_il[GMAX];
__device__ __align__(16) int    g_ir[GMAX];
__device__ __align__(16) float2 g_cf[GMAX];
__device__ unsigned int g_acc;

// ---------------------------------------------------------------------------
// int64-vs-int32 detection: OR of odd 32-bit words is 0 iff int64 (idx<4096).
// ---------------------------------------------------------------------------
__global__ void zero_kernel() { g_acc = 0u; }

__global__ void detect_kernel(const unsigned int* il, const unsigned int* ir, int G) {
    unsigned int acc = 0;
    int i = (blockIdx.x * blockDim.x + threadIdx.x) * 2 + 1;
    int stride = gridDim.x * blockDim.x * 2;
    for (; i < G; i += stride) { acc |= il[i]; acc |= ir[i]; }
    #pragma unroll
    for (int s = 16; s; s >>= 1) acc |= __shfl_xor_sync(0xffffffffu, acc, s);
    if ((threadIdx.x & 31) == 0 && acc) atomicOr(&g_acc, acc);
}

// ---------------------------------------------------------------------------
// Fold softmax(alpha) into (c_ab, c_s): y = c_ab*ab + c_s*(a+b); idx -> int32.
// ---------------------------------------------------------------------------
__global__ void prep_kernel(const unsigned int* il_raw, const unsigned int* ir_raw,
                            const float* __restrict__ alpha, int G) {
    int g = blockIdx.x * blockDim.x + threadIdx.x;
    if (g >= G) return;
    int is64 = (g_acc == 0u) ? 1 : 0;
    int il, ir;
    if (is64) { il = (int)il_raw[2 * g]; ir = (int)ir_raw[2 * g]; }
    else      { il = (int)il_raw[g];     ir = (int)ir_raw[g];     }
    g_il[g] = il;
    g_ir[g] = ir;

    float a0 = alpha[3 * g + 0], a1 = alpha[3 * g + 1], a2 = alpha[3 * g + 2];
    float m  = fmaxf(a0, fmaxf(a1, a2));
    float e0 = expf(a0 - m), e1 = expf(a1 - m), e2 = expf(a2 - m);
    float inv = 1.0f / (e0 + e1 + e2);
    float w0 = e0 * inv, w1 = e1 * inv, w2 = e2 * inv;
    g_cf[g] = make_float2(w0 - w1 - 2.0f * w2, w1 + w2);
}

// ---------------------------------------------------------------------------
// Main kernel. SMEM holds 8 rows of x TRANSPOSED: column c is two 16-B quads
// (rows 0-3, rows 4-7) at byte B = c*32 + rq*16 + (r&3)*4, swizzled
// P = B ^ ((B>>3)&0x70) so staging is bank-conflict-free. One LDS.128 gathers
// 4 rows of one column. Thread = 2 consecutive g x 8 rows = 16 outputs/iter.
// ---------------------------------------------------------------------------
__device__ __forceinline__ float4 gate4(float4 a, float4 b, float cab, float cs) {
    float4 o;
    o.x = fmaf(cab, a.x * b.x, cs * (a.x + b.x));
    o.y = fmaf(cab, a.y * b.y, cs * (a.y + b.y));
    o.z = fmaf(cab, a.z * b.z, cs * (a.z + b.z));
    o.w = fmaf(cab, a.w * b.w, cs * (a.w + b.w));
    return o;
}

__global__ __launch_bounds__(1024, 1)
void gate_kernel(const float* __restrict__ x, float* __restrict__ y,
                 int G, int gPerBlock) {
    extern __shared__ float sm[];
    char* smb = (char*)sm;
    const int tid  = threadIdx.x;
    const int warp = tid >> 5, lane = tid & 31;
    const int row0   = blockIdx.x * ROWS;
    const int gstart = blockIdx.y * gPerBlock;

    // ---- Stage: 8 rows, transposed + swizzled, conflict-free STS ----
    {
        const int rgrp = lane >> 3;            // 0..3  -> r & 3
        const int csub = lane & 7;             // 0..7
        const int rq   = warp & 1;             // which quad (rows 0-3 vs 4-7)
        const int r    = rq * 4 + rgrp;
        const float4* x4 = (const float4*)(x + (size_t)(row0 + r) * MDIM);
        #pragma unroll
        for (int i = 0; i < 8; i++) {
            int c4 = (warp >> 1) * 8 + csub + i * 128;   // c/4, covers 0..1023
            float4 v = x4[c4];
            int B0 = c4 * 128 + rq * 16 + rgrp * 4;      // byte off for j=0
            int Pb = B0 ^ ((c4 & 7) << 4);               // swizzle (j-invariant)
            *(float*)(smb + (Pb     )) = v.x;            // j offsets XOR 32*j
            *(float*)(smb + (Pb ^ 32)) = v.y;
            *(float*)(smb + (Pb ^ 64)) = v.z;
            *(float*)(smb + (Pb ^ 96)) = v.w;
        }
    }
    __syncthreads();

    float* yrow0 = y + (size_t)row0 * G;

    for (int gb = gstart + tid * 2; gb < gstart + gPerBlock; gb += 2048) {
        int2   il = *(const int2*)&g_il[gb];
        int2   ir = *(const int2*)&g_ir[gb];
        float4 cf = *(const float4*)&g_cf[gb];   // (cab0, cs0, cab1, cs1)

        // Swizzled quad addresses: P0 = c*32 ^ ((c*4)&0x70); P1 = P0 ^ 16
        int PaA = (il.x * 32) ^ ((il.x << 2) & 0x70);
        int PbA = (ir.x * 32) ^ ((ir.x << 2) & 0x70);
        int PaB = (il.y * 32) ^ ((il.y << 2) & 0x70);
        int PbB = (ir.y * 32) ^ ((ir.y << 2) & 0x70);

        float4 aA0 = *(const float4*)(smb + PaA);
        float4 aA1 = *(const float4*)(smb + (PaA ^ 16));
        float4 bA0 = *(const float4*)(smb + PbA);
        float4 bA1 = *(const float4*)(smb + (PbA ^ 16));
        float4 aB0 = *(const float4*)(smb + PaB);
        float4 aB1 = *(const float4*)(smb + (PaB ^ 16));
        float4 bB0 = *(const float4*)(smb + PbB);
        float4 bB1 = *(const float4*)(smb + (PbB ^ 16));

        float4 oA0 = gate4(aA0, bA0, cf.x, cf.y);   // g=gb,   rows 0-3
        float4 oA1 = gate4(aA1, bA1, cf.x, cf.y);   // g=gb,   rows 4-7
        float4 oB0 = gate4(aB0, bB0, cf.z, cf.w);   // g=gb+1, rows 0-3
        float4 oB1 = gate4(aB1, bB1, cf.z, cf.w);   // g=gb+1, rows 4-7

        // 8 coalesced float2 stores (warp: 32 lanes * 8 B = 256 B per row)
        float* yp = yrow0 + gb;
        *(float2*)(yp + 0 * G) = make_float2(oA0.x, oB0.x);
        *(float2*)(yp + 1 * G) = make_float2(oA0.y, oB0.y);
        *(float2*)(yp + 2 * G) = make_float2(oA0.z, oB0.z);
        *(float2*)(yp + 3 * G) = make_float2(oA0.w, oB0.w);
        *(float2*)(yp + 4 * G) = make_float2(oA1.x, oB1.x);
        *(float2*)(yp + 5 * G) = make_float2(oA1.y, oB1.y);
        *(float2*)(yp + 6 * G) = make_float2(oA1.z, oB1.z);
        *(float2*)(yp + 7 * G) = make_float2(oA1.w, oB1.w);
    }
}

// ---------------------------------------------------------------------------
extern "C" void kernel_launch(void* const* d_in, const int* in_sizes, int n_in,
                              void* d_out, int out_size) {
    const float*        x     = (const float*)d_in[0];
    const unsigned int* il    = (const unsigned int*)d_in[1];
    const unsigned int* ir    = (const unsigned int*)d_in[2];
    const float*        alpha = (const float*)d_in[3];
    float*              y     = (float*)d_out;

    const int G = in_sizes[1];               // 16384
    const int B = in_sizes[0] / MDIM;        // 4096

    zero_kernel<<<1, 1>>>();
    detect_kernel<<<32, 256>>>(il, ir, G);
    prep_kernel<<<(G + 255) / 256, 256>>>(il, ir, alpha, G);

    const int smemBytes = ROWS * MDIM * (int)sizeof(float);  // 131072 B
    cudaFuncSetAttribute(gate_kernel, cudaFuncAttributeMaxDynamicSharedMemorySize,
                         smemBytes);

    dim3 grid(B / ROWS, 2);                  // (512, 2), gPerBlock = G/2
    gate_kernel<<<grid, 1024, smemBytes>>>(x, y, G, G / 2);
}